// round 10
// baseline (speedup 1.0000x reference)
#include <cuda_runtime.h>
#include <cuda_bf16.h>
#include <cuda_fp16.h>
#include <cstdint>

// Problem constants
#define B_    16
#define T_    8192
#define D_    512
#define SPAN_ 8
#define NSEG  (16 * 1024)     // 16384 pooled rows
#define KCODE 8192
#define QOUT  ((size_t)B_ * T_ * D_)   // 67108864

#define MARGIN   0.03f
#define CAND_CAP 16

// ---------------- scratch (device globals; no allocation allowed) -----------
static __device__ __align__(256) float          g_pooled[NSEG * D_];     // 33.5MB
static __device__ __align__(256) __nv_bfloat16  g_pooled_bf[NSEG * D_];  // 16.8MB
static __device__ __align__(256) __nv_bfloat16  g_emb_bf[KCODE * D_];    // 8.4MB
static __device__ __align__(256) __half         g_score[(size_t)NSEG * KCODE]; // 268MB
static __device__ float   g_enorm[KCODE];
static __device__ int     g_cand_cnt[NSEG];
static __device__ int     g_cand[NSEG][CAND_CAP];
static __device__ int     g_best[NSEG];
static __device__ float   g_sqpart[NSEG];
static __device__ int     g_bndcount;

// ---------------- init -------------------------------------------------------
__global__ void init_kernel() {
    if (blockIdx.x == 0 && threadIdx.x == 0) g_bndcount = 0;
}

// ---------------- pooling + boundary predictor -------------------------------
__global__ __launch_bounds__(256) void pool_bnd_kernel(
    const float* __restrict__ x, const float* __restrict__ Wb,
    const float* __restrict__ bb, float* __restrict__ out_bnd, int full)
{
    __shared__ float swb[D_];
    __shared__ float sred[8][8];
    const int seg = blockIdx.x;
    const int tid = threadIdx.x;

    swb[tid]       = Wb[tid];
    swb[tid + 256] = Wb[tid + 256];
    __syncthreads();

    const float* xp = x + (size_t)seg * (SPAN_ * D_);
    float a0 = 0.f, a1 = 0.f;
    float part[SPAN_];
#pragma unroll
    for (int r = 0; r < SPAN_; r++) {
        float v0 = xp[r * D_ + tid];
        float v1 = xp[r * D_ + tid + 256];
        a0 += v0; a1 += v1;
        part[r] = v0 * swb[tid] + v1 * swb[tid + 256];
    }
    float p0 = a0 * 0.125f, p1 = a1 * 0.125f;
    g_pooled[(size_t)seg * D_ + tid]          = p0;
    g_pooled[(size_t)seg * D_ + tid + 256]    = p1;
    g_pooled_bf[(size_t)seg * D_ + tid]       = __float2bfloat16(p0);
    g_pooled_bf[(size_t)seg * D_ + tid + 256] = __float2bfloat16(p1);

    const int lane = tid & 31, w = tid >> 5;
#pragma unroll
    for (int r = 0; r < SPAN_; r++) {
        float v = part[r];
#pragma unroll
        for (int o = 16; o; o >>= 1) v += __shfl_xor_sync(0xFFFFFFFFu, v, o);
        if (lane == 0) sred[w][r] = v;
    }
    __syncthreads();

    if (tid < SPAN_) {
        float s = 0.f;
#pragma unroll
        for (int w2 = 0; w2 < 8; w2++) s += sred[w2][tid];
        float logit = s + bb[0];
        int bnd = (logit > 0.0f) ? 1 : 0;
        if (full) out_bnd[(size_t)seg * SPAN_ + tid] = (float)bnd;
        unsigned m = __ballot_sync(0x000000FFu, bnd);
        if (tid == 0) atomicAdd(&g_bndcount, __popc(m));
    }
}

// ---------------- codebook norms + bf16 convert ------------------------------
__global__ __launch_bounds__(256) void enorm_kernel(const float* __restrict__ emb) {
    const int gw   = (blockIdx.x * blockDim.x + threadIdx.x) >> 5;
    const int lane = threadIdx.x & 31;
    if (gw >= KCODE) return;
    const float* e = emb + (size_t)gw * D_;
    float s = 0.f;
#pragma unroll
    for (int d = lane; d < D_; d += 32) {
        float v = e[d]; s += v * v;
        g_emb_bf[(size_t)gw * D_ + d] = __float2bfloat16(v);
    }
#pragma unroll
    for (int o = 16; o; o >>= 1) s += __shfl_xor_sync(0xFFFFFFFFu, s, o);
    if (lane == 0) g_enorm[gw] = s;
}

// ---------------- mma.sync bf16 distance GEMM --------------------------------
// CTA tile: 128 rows x 256 cols, BK=32, 3-stage cp.async pipeline.
// 8 warps = 2(M: 64 rows) x 4(N: 64 cols); warp tile 64x64.
#define BMt 128
#define BNt 256
#define BKt 32
#define ROWB 80                       // smem row stride bytes (conflict-free)
#define STG  ((BMt + BNt) * ROWB)     // 30720 bytes per stage
#define NKIT (D_ / BKt)               // 16
#define SMEM_GEMM (3 * STG)           // 92160

__device__ __forceinline__ uint32_t smem_u32(const void* p) {
    uint32_t a;
    asm("{ .reg .u64 t; cvta.to.shared.u64 t, %1; cvt.u32.u64 %0, t; }" : "=r"(a) : "l"(p));
    return a;
}
__device__ __forceinline__ void cp16(uint32_t dst, const void* src) {
    asm volatile("cp.async.cg.shared.global [%0], [%1], 16;" :: "r"(dst), "l"(src));
}
__device__ __forceinline__ void cp_commit() { asm volatile("cp.async.commit_group;" ::: "memory"); }
template <int N> __device__ __forceinline__ void cp_wait() {
    asm volatile("cp.async.wait_group %0;" :: "n"(N) : "memory");
}
__device__ __forceinline__ void ldm_x4(uint32_t* r, uint32_t a) {
    asm volatile("ldmatrix.sync.aligned.m8n8.x4.shared.b16 {%0,%1,%2,%3}, [%4];"
        : "=r"(r[0]), "=r"(r[1]), "=r"(r[2]), "=r"(r[3]) : "r"(a));
}
__device__ __forceinline__ void mma16816(float* d, const uint32_t* a, uint32_t b0, uint32_t b1) {
    asm volatile(
        "mma.sync.aligned.m16n8k16.row.col.f32.bf16.bf16.f32 "
        "{%0,%1,%2,%3}, {%4,%5,%6,%7}, {%8,%9}, {%0,%1,%2,%3};"
        : "+f"(d[0]), "+f"(d[1]), "+f"(d[2]), "+f"(d[3])
        : "r"(a[0]), "r"(a[1]), "r"(a[2]), "r"(a[3]), "r"(b0), "r"(b1));
}

__global__ __launch_bounds__(256, 1) void gemm_mma_kernel() {
    extern __shared__ __align__(16) uint8_t sm[];
    const uint32_t smBase = smem_u32(sm);

    const int tid  = threadIdx.x;
    const int wid  = tid >> 5;
    const int lane = tid & 31;
    const int rowBase = blockIdx.y * BMt;
    const int colBase = blockIdx.x * BNt;
    const int wm = wid & 1;            // warp M block (64 rows)
    const int wn = wid >> 1;           // warp N block (64 cols)

    const char* asrc = (const char*)g_pooled_bf;
    const char* bsrc = (const char*)g_emb_bf;

    // A: 128 rows x 64B (2 cp16/thread); B: 256 rows x 64B (4 cp16/thread)
#define LOAD_STAGE(stage, k0)                                                   \
    do {                                                                        \
        _Pragma("unroll")                                                       \
        for (int l = 0; l < 2; l++) {                                           \
            int q = tid + l * 256;                                              \
            int r = q >> 2, c = q & 3;                                          \
            cp16(smBase + (stage) * STG + r * ROWB + c * 16,                    \
                 asrc + ((size_t)(rowBase + r) * D_ + (k0) + c * 8) * 2);       \
        }                                                                       \
        _Pragma("unroll")                                                       \
        for (int l = 0; l < 4; l++) {                                           \
            int q = tid + l * 256;                                              \
            int r = q >> 2, c = q & 3;                                          \
            cp16(smBase + (stage) * STG + (BMt + r) * ROWB + c * 16,            \
                 bsrc + ((size_t)(colBase + r) * D_ + (k0) + c * 8) * 2);       \
        }                                                                       \
    } while (0)

    float acc[4][8][4];
#pragma unroll
    for (int t = 0; t < 4; t++)
#pragma unroll
        for (int n = 0; n < 8; n++)
#pragma unroll
            for (int e = 0; e < 4; e++) acc[t][n][e] = 0.f;

    // per-lane ldmatrix offsets within a stage
    const int lr = lane & 15, hi = lane >> 4;
    const uint32_t aOff = (wm * 64 + lr) * ROWB + hi * 16;
    const uint32_t bOff = (BMt + wn * 64 + lr) * ROWB + hi * 16;

    LOAD_STAGE(0, 0);
    cp_commit();
    LOAD_STAGE(1, BKt);
    cp_commit();

    for (int kt = 0; kt < NKIT; kt++) {
        if (kt == NKIT - 1) { cp_wait<0>(); } else { cp_wait<1>(); }
        __syncthreads();   // stage kt ready; also: everyone done reading stage (kt+2)%3

        if (kt + 2 < NKIT) {
            LOAD_STAGE((kt + 2) % 3, (kt + 2) * BKt);
            cp_commit();
        }

        const uint32_t so = smBase + (kt % 3) * STG;
#pragma unroll
        for (int ks = 0; ks < 2; ks++) {
            uint32_t a[4][4], b[4][4];
#pragma unroll
            for (int t = 0; t < 4; t++)
                ldm_x4(a[t], so + aOff + t * (16 * ROWB) + ks * 32);
#pragma unroll
            for (int p = 0; p < 4; p++)
                ldm_x4(b[p], so + bOff + p * (16 * ROWB) + ks * 32);
#pragma unroll
            for (int t = 0; t < 4; t++)
#pragma unroll
                for (int p = 0; p < 4; p++) {
                    mma16816(acc[t][2 * p + 0], a[t], b[p][0], b[p][2]);
                    mma16816(acc[t][2 * p + 1], a[t], b[p][1], b[p][3]);
                }
        }
    }

    // epilogue: score = ||e||^2 - 2*dot, store fp16
    float en0[8], en1[8];
#pragma unroll
    for (int n = 0; n < 8; n++) {
        int c0 = colBase + wn * 64 + n * 8 + (lane & 3) * 2;
        en0[n] = __ldg(&g_enorm[c0]);
        en1[n] = __ldg(&g_enorm[c0 + 1]);
    }
#pragma unroll
    for (int t = 0; t < 4; t++) {
        int row0 = rowBase + wm * 64 + t * 16 + (lane >> 2);
#pragma unroll
        for (int n = 0; n < 8; n++) {
            int col0 = colBase + wn * 64 + n * 8 + (lane & 3) * 2;
            float s00 = fmaf(-2.f, acc[t][n][0], en0[n]);
            float s01 = fmaf(-2.f, acc[t][n][1], en1[n]);
            float s10 = fmaf(-2.f, acc[t][n][2], en0[n]);
            float s11 = fmaf(-2.f, acc[t][n][3], en1[n]);
            *(__half2*)&g_score[(size_t)row0 * KCODE + col0] = __floats2half2_rn(s00, s01);
            *(__half2*)&g_score[(size_t)(row0 + 8) * KCODE + col0] = __floats2half2_rn(s10, s11);
        }
    }
}

// ---------------- scan: per-row approx min + candidate collection ------------
__global__ __launch_bounds__(256) void scan_kernel() {
    const int wid  = threadIdx.x >> 5;
    const int lane = threadIdx.x & 31;
    const int row  = blockIdx.x * 8 + wid;

    const uint4* sp = (const uint4*)(g_score + (size_t)row * KCODE);

    // pass 1: min value
    float mn = 3.4e38f;
#pragma unroll 4
    for (int i = 0; i < 32; i++) {
        uint4 v = sp[lane + 32 * i];
        const __half2* h = (const __half2*)&v;
#pragma unroll
        for (int q = 0; q < 4; q++) {
            float2 f = __half22float2(h[q]);
            mn = fminf(mn, fminf(f.x, f.y));
        }
    }
#pragma unroll
    for (int o = 16; o; o >>= 1) mn = fminf(mn, __shfl_xor_sync(0xFFFFFFFFu, mn, o));
    const float thresh = mn + MARGIN;

    // pass 2: collect candidates (deterministic ballot/prefix ordering)
    int base = 0;
#pragma unroll 1
    for (int i = 0; i < 32; i++) {
        uint4 v = sp[lane + 32 * i];
        const __half2* h = (const __half2*)&v;
        float f[8];
#pragma unroll
        for (int q = 0; q < 4; q++) {
            float2 t = __half22float2(h[q]);
            f[2 * q] = t.x; f[2 * q + 1] = t.y;
        }
#pragma unroll
        for (int j = 0; j < 8; j++) {
            int pred = (f[j] <= thresh) ? 1 : 0;
            unsigned m = __ballot_sync(0xFFFFFFFFu, pred);
            if (pred) {
                int slot = base + __popc(m & ((1u << lane) - 1u));
                if (slot < CAND_CAP)
                    g_cand[row][slot] = (i * 32 + lane) * 8 + j;
            }
            base += __popc(m);
        }
    }
    if (lane == 0) g_cand_cnt[row] = base;
}

// ---------------- exact fp32 rescore of candidates ---------------------------
__global__ __launch_bounds__(256) void rescore_kernel(const float* __restrict__ emb) {
    const int wid  = threadIdx.x >> 5;
    const int lane = threadIdx.x & 31;
    const int row  = blockIdx.x * 8 + wid;

    const float* p = g_pooled + (size_t)row * D_;
    float pr[16];
#pragma unroll
    for (int t = 0; t < 16; t++) pr[t] = p[lane + 32 * t];

    const int cnt = g_cand_cnt[row];
    float bestS = 3.4e38f; int bestC = 0x7FFFFFFF;

    if (cnt <= CAND_CAP) {
        for (int i = 0; i < cnt; i++) {
            int k = g_cand[row][i];
            const float* e = emb + (size_t)k * D_;
            float d = 0.f;
#pragma unroll
            for (int t = 0; t < 16; t++) d = fmaf(pr[t], e[lane + 32 * t], d);
#pragma unroll
            for (int o = 16; o; o >>= 1) d += __shfl_xor_sync(0xFFFFFFFFu, d, o);
            float s = fmaf(-2.0f, d, __ldg(&g_enorm[k]));
            if (s < bestS || (s == bestS && k < bestC)) { bestS = s; bestC = k; }
        }
    } else {
        for (int k = 0; k < KCODE; k++) {
            const float* e = emb + (size_t)k * D_;
            float d = 0.f;
#pragma unroll
            for (int t = 0; t < 16; t++) d = fmaf(pr[t], e[lane + 32 * t], d);
#pragma unroll
            for (int o = 16; o; o >>= 1) d += __shfl_xor_sync(0xFFFFFFFFu, d, o);
            float s = fmaf(-2.0f, d, __ldg(&g_enorm[k]));
            if (s < bestS) { bestS = s; bestC = k; }
        }
    }
    if (lane == 0) g_best[row] = bestC;
}

// ---------------- gather + expand + e_latent partials ------------------------
__global__ __launch_bounds__(256) void scatter_kernel(
    const float* __restrict__ emb, float* __restrict__ out,
    float* __restrict__ out_idx, int full)
{
    __shared__ float sred[8];
    const int seg = blockIdx.x;
    const int tid = threadIdx.x;
    const int idx = g_best[seg];

    const float* e = emb + (size_t)idx * D_;
    float e0 = e[tid], e1 = e[tid + 256];
    float p0 = g_pooled[(size_t)seg * D_ + tid];
    float p1 = g_pooled[(size_t)seg * D_ + tid + 256];
    float d0 = e0 - p0, d1 = e1 - p1;
    float sq = d0 * d0 + d1 * d1;

    float* o = out + (size_t)seg * (SPAN_ * D_);
#pragma unroll
    for (int r = 0; r < SPAN_; r++) {
        o[r * D_ + tid]       = e0;
        o[r * D_ + tid + 256] = e1;
    }

    const int lane = tid & 31, w = tid >> 5;
#pragma unroll
    for (int o2 = 16; o2; o2 >>= 1) sq += __shfl_xor_sync(0xFFFFFFFFu, sq, o2);
    if (lane == 0) sred[w] = sq;
    __syncthreads();
    if (tid == 0) {
        float s = 0.f;
#pragma unroll
        for (int w2 = 0; w2 < 8; w2++) s += sred[w2];
        g_sqpart[seg] = s;
    }
    if (full && tid < SPAN_)
        out_idx[(size_t)seg * SPAN_ + tid] = (float)idx;
}

// ---------------- finalize loss ----------------------------------------------
__global__ __launch_bounds__(256) void finalize_kernel(float* __restrict__ out, int full) {
    if (!full) return;
    __shared__ float s[256];
    const int tid = threadIdx.x;
    float a = 0.f;
    for (int i = tid; i < NSEG; i += 256) a += g_sqpart[i];
    s[tid] = a; __syncthreads();
    for (int o = 128; o; o >>= 1) { if (tid < o) s[tid] += s[tid + o]; __syncthreads(); }
    if (tid == 0) {
        float e_latent = s[0] / (float)(NSEG * (size_t)D_);
        float bmean = (float)g_bndcount / (float)(B_ * T_);
        float d = bmean - (1.0f / (float)SPAN_);
        out[QOUT] = 0.25f * e_latent + 0.01f * d * d;
    }
}

// ---------------- launch ------------------------------------------------------
extern "C" void kernel_launch(void* const* d_in, const int* in_sizes, int n_in,
                              void* d_out, int out_size)
{
    const float* x   = (const float*)d_in[0];
    const float* emb = (const float*)d_in[1];
    const float* Wb  = (const float*)d_in[2];
    const float* bb  = (const float*)d_in[3];
    float* out = (float*)d_out;

    const int full = (out_size > (int)QOUT) ? 1 : 0;
    float* out_idx = out + QOUT + 1;
    float* out_bnd = out + QOUT + 1 + (size_t)B_ * T_;

    cudaFuncSetAttribute(gemm_mma_kernel,
                         cudaFuncAttributeMaxDynamicSharedMemorySize, SMEM_GEMM);

    init_kernel<<<1, 32>>>();
    pool_bnd_kernel<<<NSEG, 256>>>(x, Wb, bb, out_bnd, full);
    enorm_kernel<<<(KCODE * 32 + 255) / 256, 256>>>(emb);

    dim3 grid(KCODE / BNt, NSEG / BMt);   // 32 x 128 = 4096 CTAs
    gemm_mma_kernel<<<grid, 256, SMEM_GEMM>>>();

    scan_kernel<<<NSEG / 8, 256>>>();
    rescore_kernel<<<NSEG / 8, 256>>>(emb);
    scatter_kernel<<<NSEG, 256>>>(emb, out, out_idx, full);
    finalize_kernel<<<1, 256>>>(out, full);
}

// round 12
// speedup vs baseline: 1.1452x; 1.1452x over previous
#include <cuda_runtime.h>
#include <cuda_bf16.h>
#include <cuda_fp16.h>
#include <cstdint>

// Problem constants
#define B_    16
#define T_    8192
#define D_    512
#define SPAN_ 8
#define NSEG  (16 * 1024)     // 16384 pooled rows
#define KCODE 8192
#define QOUT  ((size_t)B_ * T_ * D_)   // 67108864

#define MARGIN   0.03f
#define CAND_CAP 16

// ---------------- scratch (device globals; no allocation allowed) -----------
static __device__ __align__(256) float          g_pooled[NSEG * D_];     // 33.5MB
static __device__ __align__(256) __nv_bfloat16  g_pooled_bf[NSEG * D_];  // 16.8MB
static __device__ __align__(256) __nv_bfloat16  g_emb_bf[KCODE * D_];    // 8.4MB
static __device__ __align__(256) __half         g_score[(size_t)NSEG * KCODE]; // 268MB
static __device__ float    g_enorm[KCODE];
static __device__ unsigned g_rowmin[NSEG];     // packed order-preserving fp32 min
static __device__ int      g_cand_cnt[NSEG];
static __device__ int      g_cand[NSEG][CAND_CAP];
static __device__ int      g_best[NSEG];
static __device__ float    g_sqpart[NSEG];
static __device__ int      g_bndcount;

// ---------------- init -------------------------------------------------------
__global__ void init_kernel() {
    int i = blockIdx.x * blockDim.x + threadIdx.x;
    if (i < NSEG) g_rowmin[i] = 0xFFFFFFFFu;
    if (i == 0) g_bndcount = 0;
}

// ---------------- pooling + boundary predictor -------------------------------
__global__ __launch_bounds__(256) void pool_bnd_kernel(
    const float* __restrict__ x, const float* __restrict__ Wb,
    const float* __restrict__ bb, float* __restrict__ out_bnd, int full)
{
    __shared__ float swb[D_];
    __shared__ float sred[8][8];
    const int seg = blockIdx.x;
    const int tid = threadIdx.x;

    swb[tid]       = Wb[tid];
    swb[tid + 256] = Wb[tid + 256];
    __syncthreads();

    const float* xp = x + (size_t)seg * (SPAN_ * D_);
    float a0 = 0.f, a1 = 0.f;
    float part[SPAN_];
#pragma unroll
    for (int r = 0; r < SPAN_; r++) {
        float v0 = xp[r * D_ + tid];
        float v1 = xp[r * D_ + tid + 256];
        a0 += v0; a1 += v1;
        part[r] = v0 * swb[tid] + v1 * swb[tid + 256];
    }
    float p0 = a0 * 0.125f, p1 = a1 * 0.125f;
    g_pooled[(size_t)seg * D_ + tid]          = p0;
    g_pooled[(size_t)seg * D_ + tid + 256]    = p1;
    g_pooled_bf[(size_t)seg * D_ + tid]       = __float2bfloat16(p0);
    g_pooled_bf[(size_t)seg * D_ + tid + 256] = __float2bfloat16(p1);

    const int lane = tid & 31, w = tid >> 5;
#pragma unroll
    for (int r = 0; r < SPAN_; r++) {
        float v = part[r];
#pragma unroll
        for (int o = 16; o; o >>= 1) v += __shfl_xor_sync(0xFFFFFFFFu, v, o);
        if (lane == 0) sred[w][r] = v;
    }
    __syncthreads();

    if (tid < SPAN_) {
        float s = 0.f;
#pragma unroll
        for (int w2 = 0; w2 < 8; w2++) s += sred[w2][tid];
        float logit = s + bb[0];
        int bnd = (logit > 0.0f) ? 1 : 0;
        if (full) out_bnd[(size_t)seg * SPAN_ + tid] = (float)bnd;
        unsigned m = __ballot_sync(0x000000FFu, bnd);
        if (tid == 0) atomicAdd(&g_bndcount, __popc(m));
    }
}

// ---------------- codebook norms + bf16 convert ------------------------------
__global__ __launch_bounds__(256) void enorm_kernel(const float* __restrict__ emb) {
    const int gw   = (blockIdx.x * blockDim.x + threadIdx.x) >> 5;
    const int lane = threadIdx.x & 31;
    if (gw >= KCODE) return;
    const float* e = emb + (size_t)gw * D_;
    float s = 0.f;
#pragma unroll
    for (int d = lane; d < D_; d += 32) {
        float v = e[d]; s += v * v;
        g_emb_bf[(size_t)gw * D_ + d] = __float2bfloat16(v);
    }
#pragma unroll
    for (int o = 16; o; o >>= 1) s += __shfl_xor_sync(0xFFFFFFFFu, s, o);
    if (lane == 0) g_enorm[gw] = s;
}

// ---------------- mma.sync bf16 distance GEMM --------------------------------
// Tile: 128 rows x 128 cols, BK=32, 3-stage cp.async, ONE sync per K-iter.
// 8 warps: 4(M, 32 rows) x 2(N, 64 cols). 2 CTAs/SM.
#define BMt 128
#define BNt 128
#define BKt 32
#define ROWB 80                       // smem row stride bytes (conflict-free)
#define ASTG (BMt * ROWB)             // 10240
#define STG  (2 * ASTG)               // A + B per stage = 20480
#define NKIT (D_ / BKt)               // 16
#define SMEM_GEMM (3 * STG)           // 61440

__device__ __forceinline__ uint32_t smem_u32(const void* p) {
    uint32_t a;
    asm("{ .reg .u64 t; cvta.to.shared.u64 t, %1; cvt.u32.u64 %0, t; }" : "=r"(a) : "l"(p));
    return a;
}
__device__ __forceinline__ void cp16(uint32_t dst, const void* src) {
    asm volatile("cp.async.cg.shared.global [%0], [%1], 16;" :: "r"(dst), "l"(src));
}
__device__ __forceinline__ void cp_commit() { asm volatile("cp.async.commit_group;" ::: "memory"); }
template <int N> __device__ __forceinline__ void cp_wait() {
    asm volatile("cp.async.wait_group %0;" :: "n"(N) : "memory");
}
__device__ __forceinline__ void ldm_x4(uint32_t* r, uint32_t a) {
    asm volatile("ldmatrix.sync.aligned.m8n8.x4.shared.b16 {%0,%1,%2,%3}, [%4];"
        : "=r"(r[0]), "=r"(r[1]), "=r"(r[2]), "=r"(r[3]) : "r"(a));
}
__device__ __forceinline__ void mma16816(float* d, const uint32_t* a, uint32_t b0, uint32_t b1) {
    asm volatile(
        "mma.sync.aligned.m16n8k16.row.col.f32.bf16.bf16.f32 "
        "{%0,%1,%2,%3}, {%4,%5,%6,%7}, {%8,%9}, {%0,%1,%2,%3};"
        : "+f"(d[0]), "+f"(d[1]), "+f"(d[2]), "+f"(d[3])
        : "r"(a[0]), "r"(a[1]), "r"(a[2]), "r"(a[3]), "r"(b0), "r"(b1));
}

__global__ __launch_bounds__(256, 2) void gemm_mma_kernel() {
    extern __shared__ __align__(16) uint8_t sm[];
    const uint32_t smBase = smem_u32(sm);

    const int tid  = threadIdx.x;
    const int wid  = tid >> 5;
    const int lane = tid & 31;
    const int rowBase = blockIdx.y * BMt;
    const int colBase = blockIdx.x * BNt;
    const int wm = wid & 3;            // warp row block (32 rows)
    const int nb = (wid >> 2) * 64;    // warp col base (64 cols)

    const char* asrc = (const char*)g_pooled_bf;
    const char* bsrc = (const char*)g_emb_bf;

#define LOAD_STAGE(stage, k0)                                                   \
    do {                                                                        \
        _Pragma("unroll")                                                       \
        for (int l = 0; l < 2; l++) {                                           \
            int q = tid + l * 256;                                              \
            int r = q >> 2, c = q & 3;                                          \
            cp16(smBase + (stage) * STG + r * ROWB + c * 16,                    \
                 asrc + ((size_t)(rowBase + r) * D_ + (k0) + c * 8) * 2);       \
            cp16(smBase + (stage) * STG + ASTG + r * ROWB + c * 16,             \
                 bsrc + ((size_t)(colBase + r) * D_ + (k0) + c * 8) * 2);       \
        }                                                                       \
    } while (0)

    float acc[2][8][4];
#pragma unroll
    for (int t = 0; t < 2; t++)
#pragma unroll
        for (int n = 0; n < 8; n++)
#pragma unroll
            for (int e = 0; e < 4; e++) acc[t][n][e] = 0.f;

    const int lr = lane & 15, hi = lane >> 4;
    const uint32_t aOff = (wm * 32 + lr) * ROWB + hi * 16;
    const uint32_t bOff = ASTG + (nb + lr) * ROWB + hi * 16;

    LOAD_STAGE(0, 0);
    cp_commit();
    LOAD_STAGE(1, BKt);
    cp_commit();

    int st = 0;                         // stage index = kt % 3 without division
    for (int kt = 0; kt < NKIT; kt++) {
        if (kt == NKIT - 1) { cp_wait<0>(); } else { cp_wait<1>(); }
        __syncthreads();   // stage kt arrived; stage (kt+2)%3 is free to overwrite

        if (kt + 2 < NKIT) {
            int pst = st + 2; if (pst >= 3) pst -= 3;
            LOAD_STAGE(pst, (kt + 2) * BKt);
            cp_commit();
        }

        const uint32_t so = smBase + st * STG;
#pragma unroll
        for (int ks = 0; ks < 2; ks++) {
            uint32_t a[2][4], b[4][4];
#pragma unroll
            for (int t = 0; t < 2; t++)
                ldm_x4(a[t], so + aOff + t * (16 * ROWB) + ks * 32);
#pragma unroll
            for (int p = 0; p < 4; p++)
                ldm_x4(b[p], so + bOff + p * (16 * ROWB) + ks * 32);
#pragma unroll
            for (int t = 0; t < 2; t++)
#pragma unroll
                for (int p = 0; p < 4; p++) {
                    mma16816(acc[t][2 * p + 0], a[t], b[p][0], b[p][2]);
                    mma16816(acc[t][2 * p + 1], a[t], b[p][1], b[p][3]);
                }
        }
        if (++st == 3) st = 0;
    }

    // epilogue: score = ||e||^2 - 2*dot, store fp16; fused per-row min
    float en0[8], en1[8];
#pragma unroll
    for (int n = 0; n < 8; n++) {
        int c0 = colBase + nb + n * 8 + (lane & 3) * 2;
        en0[n] = __ldg(&g_enorm[c0]);
        en1[n] = __ldg(&g_enorm[c0 + 1]);
    }
#pragma unroll
    for (int t = 0; t < 2; t++) {
        int row0 = rowBase + wm * 32 + t * 16 + (lane >> 2);
        float m0 = 3.4e38f, m1 = 3.4e38f;
#pragma unroll
        for (int n = 0; n < 8; n++) {
            int col0 = colBase + nb + n * 8 + (lane & 3) * 2;
            float s00 = fmaf(-2.f, acc[t][n][0], en0[n]);
            float s01 = fmaf(-2.f, acc[t][n][1], en1[n]);
            float s10 = fmaf(-2.f, acc[t][n][2], en0[n]);
            float s11 = fmaf(-2.f, acc[t][n][3], en1[n]);
            m0 = fminf(m0, fminf(s00, s01));
            m1 = fminf(m1, fminf(s10, s11));
            *(__half2*)&g_score[(size_t)row0 * KCODE + col0] = __floats2half2_rn(s00, s01);
            *(__half2*)&g_score[(size_t)(row0 + 8) * KCODE + col0] = __floats2half2_rn(s10, s11);
        }
        // reduce across the 4 lanes sharing each row (lane&3), then atomicMin
        m0 = fminf(m0, __shfl_xor_sync(0xFFFFFFFFu, m0, 1));
        m0 = fminf(m0, __shfl_xor_sync(0xFFFFFFFFu, m0, 2));
        m1 = fminf(m1, __shfl_xor_sync(0xFFFFFFFFu, m1, 1));
        m1 = fminf(m1, __shfl_xor_sync(0xFFFFFFFFu, m1, 2));
        if ((lane & 3) == 0) {
            unsigned u0 = __float_as_uint(m0);
            u0 ^= (u0 >> 31) ? 0xFFFFFFFFu : 0x80000000u;
            atomicMin(&g_rowmin[row0], u0);
            unsigned u1 = __float_as_uint(m1);
            u1 ^= (u1 >> 31) ? 0xFFFFFFFFu : 0x80000000u;
            atomicMin(&g_rowmin[row0 + 8], u1);
        }
    }
}

// ---------------- scan: single-pass candidate collection ---------------------
__global__ __launch_bounds__(256) void scan_kernel() {
    const int wid  = threadIdx.x >> 5;
    const int lane = threadIdx.x & 31;
    const int row  = blockIdx.x * 8 + wid;

    unsigned u = g_rowmin[row];
    u = (u & 0x80000000u) ? (u ^ 0x80000000u) : ~u;
    const float thresh = __uint_as_float(u) + MARGIN;

    const uint4* sp = (const uint4*)(g_score + (size_t)row * KCODE);

    int base = 0;
#pragma unroll 1
    for (int i = 0; i < 32; i++) {
        uint4 v = sp[lane + 32 * i];
        const __half2* h = (const __half2*)&v;
        float f[8];
#pragma unroll
        for (int q = 0; q < 4; q++) {
            float2 t = __half22float2(h[q]);
            f[2 * q] = t.x; f[2 * q + 1] = t.y;
        }
#pragma unroll
        for (int j = 0; j < 8; j++) {
            int pred = (f[j] <= thresh) ? 1 : 0;
            unsigned m = __ballot_sync(0xFFFFFFFFu, pred);
            if (pred) {
                int slot = base + __popc(m & ((1u << lane) - 1u));
                if (slot < CAND_CAP)
                    g_cand[row][slot] = (i * 32 + lane) * 8 + j;
            }
            base += __popc(m);
        }
    }
    if (lane == 0) g_cand_cnt[row] = base;
}

// ---------------- exact fp32 rescore of candidates ---------------------------
__global__ __launch_bounds__(256) void rescore_kernel(const float* __restrict__ emb) {
    const int wid  = threadIdx.x >> 5;
    const int lane = threadIdx.x & 31;
    const int row  = blockIdx.x * 8 + wid;

    const float* p = g_pooled + (size_t)row * D_;
    float pr[16];
#pragma unroll
    for (int t = 0; t < 16; t++) pr[t] = p[lane + 32 * t];

    const int cnt = g_cand_cnt[row];
    float bestS = 3.4e38f; int bestC = 0x7FFFFFFF;

    if (cnt <= CAND_CAP) {
        for (int i = 0; i < cnt; i++) {
            int k = g_cand[row][i];
            const float* e = emb + (size_t)k * D_;
            float d = 0.f;
#pragma unroll
            for (int t = 0; t < 16; t++) d = fmaf(pr[t], e[lane + 32 * t], d);
#pragma unroll
            for (int o = 16; o; o >>= 1) d += __shfl_xor_sync(0xFFFFFFFFu, d, o);
            float s = fmaf(-2.0f, d, __ldg(&g_enorm[k]));
            if (s < bestS || (s == bestS && k < bestC)) { bestS = s; bestC = k; }
        }
    } else {
        for (int k = 0; k < KCODE; k++) {
            const float* e = emb + (size_t)k * D_;
            float d = 0.f;
#pragma unroll
            for (int t = 0; t < 16; t++) d = fmaf(pr[t], e[lane + 32 * t], d);
#pragma unroll
            for (int o = 16; o; o >>= 1) d += __shfl_xor_sync(0xFFFFFFFFu, d, o);
            float s = fmaf(-2.0f, d, __ldg(&g_enorm[k]));
            if (s < bestS) { bestS = s; bestC = k; }
        }
    }
    if (lane == 0) g_best[row] = bestC;
}

// ---------------- gather + expand + e_latent partials ------------------------
__global__ __launch_bounds__(256) void scatter_kernel(
    const float* __restrict__ emb, float* __restrict__ out,
    float* __restrict__ out_idx, int full)
{
    __shared__ float sred[8];
    const int seg = blockIdx.x;
    const int tid = threadIdx.x;
    const int idx = g_best[seg];

    const float* e = emb + (size_t)idx * D_;
    float e0 = e[tid], e1 = e[tid + 256];
    float p0 = g_pooled[(size_t)seg * D_ + tid];
    float p1 = g_pooled[(size_t)seg * D_ + tid + 256];
    float d0 = e0 - p0, d1 = e1 - p1;
    float sq = d0 * d0 + d1 * d1;

    float* o = out + (size_t)seg * (SPAN_ * D_);
#pragma unroll
    for (int r = 0; r < SPAN_; r++) {
        o[r * D_ + tid]       = e0;
        o[r * D_ + tid + 256] = e1;
    }

    const int lane = tid & 31, w = tid >> 5;
#pragma unroll
    for (int o2 = 16; o2; o2 >>= 1) sq += __shfl_xor_sync(0xFFFFFFFFu, sq, o2);
    if (lane == 0) sred[w] = sq;
    __syncthreads();
    if (tid == 0) {
        float s = 0.f;
#pragma unroll
        for (int w2 = 0; w2 < 8; w2++) s += sred[w2];
        g_sqpart[seg] = s;
    }
    if (full && tid < SPAN_)
        out_idx[(size_t)seg * SPAN_ + tid] = (float)idx;
}

// ---------------- finalize loss ----------------------------------------------
__global__ __launch_bounds__(256) void finalize_kernel(float* __restrict__ out, int full) {
    if (!full) return;
    __shared__ float s[256];
    const int tid = threadIdx.x;
    float a = 0.f;
    for (int i = tid; i < NSEG; i += 256) a += g_sqpart[i];
    s[tid] = a; __syncthreads();
    for (int o = 128; o; o >>= 1) { if (tid < o) s[tid] += s[tid + o]; __syncthreads(); }
    if (tid == 0) {
        float e_latent = s[0] / (float)(NSEG * (size_t)D_);
        float bmean = (float)g_bndcount / (float)(B_ * T_);
        float d = bmean - (1.0f / (float)SPAN_);
        out[QOUT] = 0.25f * e_latent + 0.01f * d * d;
    }
}

// ---------------- launch ------------------------------------------------------
extern "C" void kernel_launch(void* const* d_in, const int* in_sizes, int n_in,
                              void* d_out, int out_size)
{
    const float* x   = (const float*)d_in[0];
    const float* emb = (const float*)d_in[1];
    const float* Wb  = (const float*)d_in[2];
    const float* bb  = (const float*)d_in[3];
    float* out = (float*)d_out;

    const int full = (out_size > (int)QOUT) ? 1 : 0;
    float* out_idx = out + QOUT + 1;
    float* out_bnd = out + QOUT + 1 + (size_t)B_ * T_;

    cudaFuncSetAttribute(gemm_mma_kernel,
                         cudaFuncAttributeMaxDynamicSharedMemorySize, SMEM_GEMM);

    init_kernel<<<NSEG / 256, 256>>>();
    pool_bnd_kernel<<<NSEG, 256>>>(x, Wb, bb, out_bnd, full);
    enorm_kernel<<<(KCODE * 32 + 255) / 256, 256>>>(emb);

    dim3 grid(KCODE / BNt, NSEG / BMt);   // 64 x 128 = 8192 CTAs
    gemm_mma_kernel<<<grid, 256, SMEM_GEMM>>>();

    scan_kernel<<<NSEG / 8, 256>>>();
    rescore_kernel<<<NSEG / 8, 256>>>(emb);
    scatter_kernel<<<NSEG, 256>>>(emb, out, out_idx, full);
    finalize_kernel<<<1, 256>>>(out, full);
}